// round 5
// baseline (speedup 1.0000x reference)
#include <cuda_runtime.h>
#include <math.h>
#include <stdint.h>

#define BATCH 256
#define VOCAB 128000
#define NBINS 8192
#define CAP   4096
#define NEG_INF __int_as_float(0xff800000)
typedef unsigned long long ull;

// ---------------- scratch (device globals; no allocations allowed) ----------
__device__ float    g_histG[BATCH * NBINS];          // 8MB merged histograms
__device__ ull      g_keep[(size_t)BATCH * VOCAB];   // kept elems (raw, v)
__device__ ull      g_cand[BATCH * CAP];             // boundary-bin candidates
__device__ int      g_kcount[BATCH];
__device__ int      g_ccount[BATCH];
__device__ unsigned g_rmk[BATCH];                    // okey(row max value)
__device__ unsigned g_amin[BATCH];                   // argmax (first occurrence)
__device__ ull      g_best[BATCH];                   // (okey(score)<<32)|~v
__device__ float    g_sk[BATCH];                     // kept mass (Ms-anchored)
__device__ int      g_Bstar[BATCH];
__device__ double   g_cumAbove[BATCH];
__device__ double   g_Z[BATCH];
__device__ ull      g_cut[BATCH];                    // keep <=> (okey(s),v) >= cut

// monotone float<->uint key (total order)
__device__ __forceinline__ unsigned okey(float f){
    unsigned b = __float_as_uint(f);
    return b ^ ((b & 0x80000000u) ? 0xFFFFFFFFu : 0x80000000u);
}
__device__ __forceinline__ float key_to_float(unsigned k){
    unsigned b = (k & 0x80000000u) ? (k ^ 0x80000000u) : ~k;
    return __uint_as_float(b);
}

// jax threefry2x32-20, key = (0, 42)
__device__ __forceinline__ void threefry(unsigned c0, unsigned c1,
                                         unsigned &o0, unsigned &o1){
    const unsigned k0 = 0u, k1 = 42u;
    const unsigned k2 = 0x1BD11BDAu ^ k0 ^ k1;
    unsigned x0 = c0 + k0, x1 = c1 + k1;
#define TFR(r) { x0 += x1; x1 = ((x1 << r) | (x1 >> (32 - r))); x1 ^= x0; }
    TFR(13) TFR(15) TFR(26) TFR(6)   x0 += k1; x1 += k2 + 1u;
    TFR(17) TFR(29) TFR(16) TFR(24)  x0 += k2; x1 += k0 + 2u;
    TFR(13) TFR(15) TFR(26) TFR(6)   x0 += k0; x1 += k1 + 3u;
    TFR(17) TFR(29) TFR(16) TFR(24)  x0 += k1; x1 += k2 + 4u;
    TFR(13) TFR(15) TFR(26) TFR(6)   x0 += k2; x1 += k0 + 5u;
#undef TFR
    o0 = x0; o1 = x1;
}
__device__ __forceinline__ unsigned jax_bits32(unsigned i){
    unsigned o0, o1; threefry(0u, i, o0, o1); return o0 ^ o1;
}
__device__ __forceinline__ float gumbel_from_bits(unsigned bits){
    float u = __uint_as_float((bits >> 9) | 0x3f800000u) - 1.0f;
    if (u <= 0.0f) u = 1.17549435e-38f;
    float inner = -log1pf(u - 1.0f);   // == -log(u) exactly
    return -logf(inner);
}

// ---------------- K0: init ---------------------------------------------------
__global__ void k0_init(){
    size_t id = (size_t)blockIdx.x * 1024 + threadIdx.x;
    float4* h4 = (float4*)g_histG;
    if (id < (size_t)BATCH * NBINS / 4) h4[id] = make_float4(0.f,0.f,0.f,0.f);
    if (id < BATCH){
        g_rmk[id] = 0u; g_amin[id] = 0xFFFFFFFFu;
        g_best[id] = 0ULL; g_sk[id] = 0.0f;
        g_kcount[id] = 0; g_ccount[id] = 0;
    }
}

// ---------------- K2a: raw-key histogram + row max (MLP-4 batched) -----------
__global__ void k2a_hist(const float* __restrict__ logits,
                         const float* __restrict__ temps){
    int row = blockIdx.y, part = blockIdx.x;        // 4 parts of 32000 elems
    __shared__ float bins[NBINS];
    __shared__ float sm[512];
    for (int i = threadIdx.x; i < NBINS; i += 512) bins[i] = 0.0f;
    __syncthreads();

    float t = temps[row]; float ts = (t == 0.0f) ? 1.0f : t;
    float inv = 1.0f / ts;
    const float4* x4 = (const float4*)(logits + (size_t)row * VOCAB + part * 32000);
    float vmax = NEG_INF;
    // 8000 float4 per block; 4 iterations of 4 batched loads (stride 512)
    for (int base = threadIdx.x; base < 8000; base += 2048){
        float4 f[4]; bool ok[4];
#pragma unroll
        for (int k = 0; k < 4; k++){
            int i = base + k * 512;
            ok[k] = (i < 8000);
            if (ok[k]) f[k] = x4[i];
        }
#pragma unroll
        for (int k = 0; k < 4; k++){
            if (!ok[k]) continue;
            float vals[4] = {f[k].x, f[k].y, f[k].z, f[k].w};
#pragma unroll
            for (int j = 0; j < 4; j++){
                float x = vals[j];
                vmax = fmaxf(vmax, x);
                unsigned kx = okey(x);
                unsigned bin = kx >> 19;
                float xref = key_to_float((bin << 19) | 0x7FFFFu);
                atomicAdd(&bins[bin], __expf((x - xref) * inv));
            }
        }
    }
    sm[threadIdx.x] = vmax; __syncthreads();
    for (int s = 256; s > 0; s >>= 1){
        if (threadIdx.x < s) sm[threadIdx.x] = fmaxf(sm[threadIdx.x], sm[threadIdx.x + s]);
        __syncthreads();
    }
    if (threadIdx.x == 0) atomicMax(&g_rmk[row], okey(sm[0]));
    float* gh = g_histG + (size_t)row * NBINS;
    for (int i = threadIdx.x; i < NBINS; i += 512)
        if (bins[i] != 0.0f) atomicAdd(&gh[i], bins[i]);
}

// ---------------- K2b: rescale + suffix scan -> boundary bin -----------------
__global__ void k2b_scan(const float* __restrict__ temps,
                         const float* __restrict__ topps){
    int row = blockIdx.x; int tid = threadIdx.x;   // 1024 threads
    __shared__ double sarr[1024];
    __shared__ int    sbi[1024];
    __shared__ double sZ;

    float t = temps[row]; float ts = (t == 0.0f) ? 1.0f : t;
    float xmax = key_to_float(g_rmk[row]);
    double invd = 1.0 / (double)ts;

    const float4* gh4 = (const float4*)(g_histG + (size_t)row * NBINS);
    float4 h0 = gh4[tid * 2], h1 = gh4[tid * 2 + 1];
    float hv[8] = {h0.x, h0.y, h0.z, h0.w, h1.x, h1.y, h1.z, h1.w};

    int base = tid * 8;
    double mv[8]; double csum = 0.0;
#pragma unroll
    for (int j = 0; j < 8; j++){
        double m = 0.0;
        if (hv[j] > 0.0f){
            float xref = key_to_float(((unsigned)(base + j) << 19) | 0x7FFFFu);
            m = (double)hv[j] * exp(((double)xref - (double)xmax) * invd);
        }
        mv[j] = m; csum += m;
    }
    sarr[tid] = csum; __syncthreads();
    for (int off = 1; off < 1024; off <<= 1){
        double v = sarr[tid];
        double a = (tid + off < 1024) ? sarr[tid + off] : 0.0;
        __syncthreads();
        sarr[tid] = v + a;
        __syncthreads();
    }
    double above = sarr[tid] - csum;
    if (tid == 0) sZ = sarr[0];
    __syncthreads();
    double Z = sZ;

    float p = fminf(fmaxf(topps[row], 0.0f), 1.0f);
    double pZ = (double)p * Z;

    int bestj = -1; double bestAbove = 0.0;
    double run = above;
    for (int j = 7; j >= 0; j--){
        double s = mv[j];
        if (run + s > pZ){ bestj = base + j; bestAbove = run; break; }
        run += s;
    }
    __syncthreads();
    sbi[tid] = bestj; sarr[tid] = bestAbove; __syncthreads();
    for (int s2 = 512; s2 > 0; s2 >>= 1){
        if (tid < s2 && sbi[tid + s2] > sbi[tid]){
            sbi[tid] = sbi[tid + s2];
            sarr[tid] = sarr[tid + s2];
        }
        __syncthreads();
    }
    if (tid == 0){
        int B = sbi[0];
        if (B < 0){ B = 0; sarr[0] = 0.0; }   // unreachable guard (Z >= ~1)
        g_Bstar[row] = B;
        g_cumAbove[row] = sarr[0];
        g_Z[row] = Z;
    }
}

// ---------------- K3a: gather keeps + candidates + argmax (MLP-4) ------------
__global__ void k3a_gather(const float* __restrict__ logits,
                           const float* __restrict__ temps){
    int row = blockIdx.y;
    int Bstar = g_Bstar[row];
    unsigned kmax = g_rmk[row];
    float t = temps[row]; float ts = (t == 0.0f) ? 1.0f : t;
    int base0 = blockIdx.x * 16000;                  // 8 chunks per row
    const float4* x4 = (const float4*)(logits + (size_t)row * VOCAB + base0);
    int lane = threadIdx.x & 31;
    unsigned lmask = (1u << lane) - 1u;
    ull* keepRow = g_keep + (size_t)row * VOCAB;
    ull* candRow = g_cand + (size_t)row * CAP;

    // 4000 float4 per block; uniform 4 iterations; positions base + k*256
    for (int base = threadIdx.x; base < 4000; base += 1024){
        float4 f[4]; bool ok[4];
#pragma unroll
        for (int k = 0; k < 4; k++){
            int i = base + k * 256;
            ok[k] = (i < 4000);
            if (ok[k]) f[k] = x4[i];
        }
#pragma unroll
        for (int k = 0; k < 4; k++){
            unsigned v0 = (unsigned)(base0 + (base + k * 256) * 4);
            float vals[4] = {f[k].x, f[k].y, f[k].z, f[k].w};
#pragma unroll
            for (int j = 0; j < 4; j++){
                unsigned kx = ok[k] ? okey(vals[j]) : 0u;
                int bin = (int)(kx >> 19);
                bool isK = ok[k] && (bin > Bstar);
                bool isC = ok[k] && (bin == Bstar);
                unsigned mK = __ballot_sync(0xFFFFFFFFu, isK);
                if (mK){
                    int ldr = __ffs(mK) - 1;
                    int b0;
                    if (lane == ldr) b0 = atomicAdd(&g_kcount[row], __popc(mK));
                    b0 = __shfl_sync(0xFFFFFFFFu, b0, ldr);
                    if (isK)
                        keepRow[b0 + __popc(mK & lmask)] =
                            ((ull)kx << 32) | (v0 + j);
                }
                unsigned mC = __ballot_sync(0xFFFFFFFFu, isC);
                if (mC){
                    int ldr = __ffs(mC) - 1;
                    int b0;
                    if (lane == ldr) b0 = atomicAdd(&g_ccount[row], __popc(mC));
                    b0 = __shfl_sync(0xFFFFFFFFu, b0, ldr);
                    if (isC){
                        int pos = b0 + __popc(mC & lmask);
                        if (pos < CAP){
                            float s = __fdiv_rn(vals[j], ts);
                            candRow[pos] = ((ull)okey(s) << 32) | (v0 + j);
                        }
                    }
                }
                if (ok[k] && kx == kmax) atomicMin(&g_amin[row], v0 + j);
            }
        }
    }
}

// ---------------- K3b: sort candidates + exact cutoff ------------------------
__global__ void k3b_cut(const float* __restrict__ temps,
                        const float* __restrict__ topps){
    int row = blockIdx.x;
    int Bstar = g_Bstar[row];
    __shared__ ull keys[CAP];                 // 32KB
    __shared__ double sarr[1024];
    __shared__ int sli[1024];

    float t = temps[row]; float ts = (t == 0.0f) ? 1.0f : t;
    double Ms = (double)__fdiv_rn(key_to_float(g_rmk[row]), ts);
    int count = min(g_ccount[row], CAP);
    if (count == 0){                          // guard; ~never (bin has mass)
        if (threadIdx.x == 0){
            float xLo = key_to_float((unsigned)Bstar << 19);
            g_cut[row] = ((ull)okey(__fdiv_rn(xLo, ts)) << 32);
        }
        return;
    }
    int n = 1; while (n < count) n <<= 1; if (n < 2) n = 2;
    for (int i = threadIdx.x; i < n; i += blockDim.x)
        keys[i] = (i < count) ? g_cand[(size_t)row * CAP + i] : 0ULL;
    __syncthreads();

    // bitonic sort DESCENDING on packed (okey(s), idx)
    for (int k2 = 2; k2 <= n; k2 <<= 1){
        for (int j = k2 >> 1; j > 0; j >>= 1){
            for (int i = threadIdx.x; i < n; i += blockDim.x){
                int ixj = i ^ j;
                if (ixj > i){
                    ull a = keys[i], b = keys[ixj];
                    bool seg = ((i & k2) == 0);
                    if (seg ? (a < b) : (a > b)){ keys[i] = b; keys[ixj] = a; }
                }
            }
            __syncthreads();
        }
    }

    double pZ = (double)fminf(fmaxf(topps[row], 0.0f), 1.0f) * g_Z[row];
    double cumAbove = g_cumAbove[row];
    int m = (n + blockDim.x - 1) / blockDim.x;   // <= 4
    int lo = threadIdx.x * m;
    double ev[4];
    double ls = 0.0;
    for (int q = 0; q < m; q++){
        int i = lo + q; double e = 0.0;
        if (i < count){
            double sv = (double)key_to_float((unsigned)(keys[i] >> 32));
            e = exp(sv - Ms);
        }
        ev[q] = e; ls += e;
    }
    sarr[threadIdx.x] = ls; __syncthreads();
    for (int off = 1; off < 1024; off <<= 1){
        double v = sarr[threadIdx.x];
        double a = (threadIdx.x >= off) ? sarr[threadIdx.x - off] : 0.0;
        __syncthreads();
        sarr[threadIdx.x] = v + a;
        __syncthreads();
    }
    double run = sarr[threadIdx.x] - ls + cumAbove;
    int lastKept = -1;
    for (int q = 0; q < m; q++){
        int i = lo + q;
        run += ev[q];
        if (i < count && run <= pZ) lastKept = i;
    }
    sli[threadIdx.x] = lastKept; __syncthreads();
    for (int s2 = 512; s2 > 0; s2 >>= 1){
        if (threadIdx.x < s2)
            sli[threadIdx.x] = max(sli[threadIdx.x], sli[threadIdx.x + s2]);
        __syncthreads();
    }
    if (threadIdx.x == 0){
        int iL = sli[0];
        ull C;
        if (iL >= 0)             C = keys[iL];
        else if (cumAbove > 0.0){
            float xHi = key_to_float((unsigned)(Bstar + 1) << 19);
            C = ((ull)okey(__fdiv_rn(xHi, ts)) << 32);
        } else                   C = keys[0];  // force-keep top element
        g_cut[row] = C;
    }
}

// ---------------- K4a: gumbel-max over COMPACTED kept set --------------------
__global__ void k4a_compact(const float* __restrict__ temps){
    int row = blockIdx.y;
    int nk = g_kcount[row];
    int nc = min(g_ccount[row], CAP);
    int tot = nk + nc;
    float t = temps[row]; float ts = (t == 0.0f) ? 1.0f : t;
    float Ms = __fdiv_rn(key_to_float(g_rmk[row]), ts);
    ull C = g_cut[row];
    unsigned iBase = (unsigned)row * (unsigned)VOCAB;
    const ull* keepRow = g_keep + (size_t)row * VOCAB;
    const ull* candRow = g_cand + (size_t)row * CAP;

    float sk = 0.0f; ull bestp = 0ULL;
    for (int i = blockIdx.x * 256 + threadIdx.x; i < tot; i += 1024){
        float s; unsigned v; bool kept;
        if (i < nk){
            ull e = keepRow[i];
            v = (unsigned)e;
            s = __fdiv_rn(key_to_float((unsigned)(e >> 32)), ts);
            kept = true;
        } else {
            ull e = candRow[i - nk];
            v = (unsigned)e;
            s = key_to_float((unsigned)(e >> 32));
            kept = (e >= C);
        }
        if (kept){
            sk += __expf(s - Ms);
            float sc = s + gumbel_from_bits(jax_bits32(iBase + v));
            ull p = ((ull)okey(sc) << 32) | (unsigned)(~v);
            if (p > bestp) bestp = p;
        }
    }

    __shared__ ull sp[256];
    __shared__ float sv[256];
    sp[threadIdx.x] = bestp; sv[threadIdx.x] = sk;
    __syncthreads();
    for (int s = 128; s > 0; s >>= 1){
        if (threadIdx.x < s){
            if (sp[threadIdx.x + s] > sp[threadIdx.x])
                sp[threadIdx.x] = sp[threadIdx.x + s];
            sv[threadIdx.x] += sv[threadIdx.x + s];
        }
        __syncthreads();
    }
    if (threadIdx.x == 0){
        if (sp[0] != 0ULL) atomicMax(&g_best[row], sp[0]);
        if (sv[0] != 0.0f) atomicAdd(&g_sk[row], sv[0]);
    }
}

// ---------------- K4b: finalize ----------------------------------------------
__global__ void k4b_final(const float* __restrict__ logits,
                          const float* __restrict__ temps,
                          float* __restrict__ out){
    int row = threadIdx.x;   // 256 threads, 1 block
    if (row >= BATCH) return;
    float t = temps[row]; float ts = (t == 0.0f) ? 1.0f : t;
    float Ms = __fdiv_rn(key_to_float(g_rmk[row]), ts);
    unsigned greedy = g_amin[row];
    ull C = g_cut[row];
    unsigned tok;
    if (t == 0.0f) tok = greedy;
    else {
        unsigned cand = ~(unsigned)(g_best[row] & 0xFFFFFFFFu);
        tok = (cand < (unsigned)VOCAB) ? cand : greedy;
    }
    float stok = __fdiv_rn(logits[(size_t)row * VOCAB + tok], ts);
    ull pT = ((ull)okey(stok) << 32) | tok;
    float sel = (pT >= C) ? stok : NEG_INF;
    float skv = g_sk[row];
    float lp = (skv > 0.0f) ? (sel - (Ms + logf(skv))) : 0.0f;
    out[row]          = (float)tok;
    out[BATCH + row]  = lp;
}

// ---------------- launch -----------------------------------------------------
extern "C" void kernel_launch(void* const* d_in, const int* in_sizes, int n_in,
                              void* d_out, int out_size){
    const float* logits = (const float*)d_in[0];
    const float* temps  = (const float*)d_in[1];
    const float* topps  = (const float*)d_in[2];
    float* out = (float*)d_out;

    k0_init    <<<512, 1024>>>();
    k2a_hist   <<<dim3(4, BATCH), 512>>>(logits, temps);
    k2b_scan   <<<BATCH, 1024>>>(temps, topps);
    k3a_gather <<<dim3(8, BATCH), 256>>>(logits, temps);
    k3b_cut    <<<BATCH, 1024>>>(temps, topps);
    k4a_compact<<<dim3(4, BATCH), 256>>>(temps);
    k4b_final  <<<1, 256>>>(logits, temps, out);
}

// round 6
// speedup vs baseline: 1.1667x; 1.1667x over previous
#include <cuda_runtime.h>
#include <math.h>
#include <stdint.h>

#define BATCH 256
#define VOCAB 128000
#define NBINS 8192
#define CAP   4096
#define SBUF  4096
#define NEG_INF __int_as_float(0xff800000)
typedef unsigned long long ull;

// ---------------- scratch (device globals; no allocations allowed) ----------
__device__ float    g_histG[BATCH * NBINS];          // 8MB merged histograms
__device__ ull      g_keep[(size_t)BATCH * VOCAB];   // kept elems (raw key, v)
__device__ ull      g_cand[BATCH * CAP];             // boundary-bin candidates
__device__ int      g_kcount[BATCH];
__device__ int      g_ccount[BATCH];
__device__ unsigned g_rmk[BATCH];                    // okey(row max value)
__device__ unsigned g_amin[BATCH];                   // argmax (first occurrence)
__device__ ull      g_best[BATCH];                   // (okey(score)<<32)|~v
__device__ float    g_sk[BATCH];                     // kept mass (Ms-anchored)
__device__ int      g_Bstar[BATCH];                  // -2 = degenerate row
__device__ double   g_cumAbove[BATCH];
__device__ double   g_Z[BATCH];
__device__ ull      g_cut[BATCH];                    // keep <=> (okey(s),v) >= cut

// monotone float<->uint key (total order)
__device__ __forceinline__ unsigned okey(float f){
    unsigned b = __float_as_uint(f);
    return b ^ ((b & 0x80000000u) ? 0xFFFFFFFFu : 0x80000000u);
}
__device__ __forceinline__ float key_to_float(unsigned k){
    unsigned b = (k & 0x80000000u) ? (k ^ 0x80000000u) : ~k;
    return __uint_as_float(b);
}
__device__ __forceinline__ float ex2(float x){      // single MUFU.EX2
    float r; asm("ex2.approx.f32 %0, %1;" : "=f"(r) : "f"(x)); return r;
}

// jax threefry2x32-20, key = (0, 42)
__device__ __forceinline__ void threefry(unsigned c0, unsigned c1,
                                         unsigned &o0, unsigned &o1){
    const unsigned k0 = 0u, k1 = 42u;
    const unsigned k2 = 0x1BD11BDAu ^ k0 ^ k1;
    unsigned x0 = c0 + k0, x1 = c1 + k1;
#define TFR(r) { x0 += x1; x1 = ((x1 << r) | (x1 >> (32 - r))); x1 ^= x0; }
    TFR(13) TFR(15) TFR(26) TFR(6)   x0 += k1; x1 += k2 + 1u;
    TFR(17) TFR(29) TFR(16) TFR(24)  x0 += k2; x1 += k0 + 2u;
    TFR(13) TFR(15) TFR(26) TFR(6)   x0 += k0; x1 += k1 + 3u;
    TFR(17) TFR(29) TFR(16) TFR(24)  x0 += k1; x1 += k2 + 4u;
    TFR(13) TFR(15) TFR(26) TFR(6)   x0 += k2; x1 += k0 + 5u;
#undef TFR
    o0 = x0; o1 = x1;
}
__device__ __forceinline__ unsigned jax_bits32(unsigned i){
    unsigned o0, o1; threefry(0u, i, o0, o1); return o0 ^ o1;
}
__device__ __forceinline__ float gumbel_from_bits(unsigned bits){
    float u = __uint_as_float((bits >> 9) | 0x3f800000u) - 1.0f;
    if (u <= 0.0f) u = 1.17549435e-38f;
    float inner = -log1pf(u - 1.0f);   // == -log(u) exactly
    return -logf(inner);
}

// ---------------- K0: init ---------------------------------------------------
__global__ void k0_init(){
    size_t id = (size_t)blockIdx.x * 1024 + threadIdx.x;
    float4* h4 = (float4*)g_histG;
    if (id < (size_t)BATCH * NBINS / 4) h4[id] = make_float4(0.f,0.f,0.f,0.f);
    if (id < BATCH){
        g_rmk[id] = 0u; g_amin[id] = 0xFFFFFFFFu;
        g_best[id] = 0ULL; g_sk[id] = 0.0f;
        g_kcount[id] = 0; g_ccount[id] = 0;
    }
}

// ---------------- K2a: raw-key weighted histogram + row max ------------------
__global__ void k2a_hist(const float* __restrict__ logits,
                         const float* __restrict__ temps){
    int row = blockIdx.y, part = blockIdx.x;        // 4 parts of 32000 elems
    __shared__ float bins[NBINS];                   // 32KB
    __shared__ float xref[NBINS];                   // 32KB bin top-edge values
    __shared__ float sm[512];
    for (int i = threadIdx.x; i < NBINS; i += 512){
        bins[i] = 0.0f;
        xref[i] = key_to_float(((unsigned)i << 19) | 0x7FFFFu);
    }
    __syncthreads();

    float t = temps[row]; float ts = (t == 0.0f) ? 1.0f : t;
    float c1 = __fdividef(1.4426950408889634f, ts);     // log2e / ts
    const float4* x4 = (const float4*)(logits + (size_t)row * VOCAB + part * 32000);
    float vmax = NEG_INF;
    for (int base = threadIdx.x; base < 8000; base += 2048){
        float4 f[4]; bool ok[4];
#pragma unroll
        for (int k = 0; k < 4; k++){
            int i = base + k * 512;
            ok[k] = (i < 8000);
            if (ok[k]) f[k] = x4[i];
        }
#pragma unroll
        for (int k = 0; k < 4; k++){
            if (!ok[k]) continue;
            float vals[4] = {f[k].x, f[k].y, f[k].z, f[k].w};
#pragma unroll
            for (int j = 0; j < 4; j++){
                float x = vals[j];
                vmax = fmaxf(vmax, x);
                unsigned bin = okey(x) >> 19;
                float d = x - xref[bin];            // exact (same binade)
                atomicAdd(&bins[bin], ex2(d * c1));
            }
        }
    }
    sm[threadIdx.x] = vmax; __syncthreads();
    for (int s = 256; s > 0; s >>= 1){
        if (threadIdx.x < s) sm[threadIdx.x] = fmaxf(sm[threadIdx.x], sm[threadIdx.x + s]);
        __syncthreads();
    }
    if (threadIdx.x == 0) atomicMax(&g_rmk[row], okey(sm[0]));
    float* gh = g_histG + (size_t)row * NBINS;
    for (int i = threadIdx.x; i < NBINS; i += 512)
        if (bins[i] != 0.0f) atomicAdd(&gh[i], bins[i]);
}

// ---------------- K2b: rescale + suffix scan -> boundary bin -----------------
__global__ void k2b_scan(const float* __restrict__ temps,
                         const float* __restrict__ topps){
    int row = blockIdx.x; int tid = threadIdx.x;   // 1024 threads
    __shared__ double sarr[1024];
    __shared__ int    sbi[1024];
    __shared__ double sZ;

    float t = temps[row]; float ts = (t == 0.0f) ? 1.0f : t;
    unsigned kmax = g_rmk[row];
    float xmax = key_to_float(kmax);
    double invd = 1.0 / (double)ts;

    const float4* gh4 = (const float4*)(g_histG + (size_t)row * NBINS);
    float4 h0 = gh4[tid * 2], h1 = gh4[tid * 2 + 1];
    float hv[8] = {h0.x, h0.y, h0.z, h0.w, h1.x, h1.y, h1.z, h1.w};

    int base = tid * 8;
    double mv[8]; double csum = 0.0;
#pragma unroll
    for (int j = 0; j < 8; j++){
        double m = 0.0;
        if (hv[j] > 0.0f){
            float xr = key_to_float(((unsigned)(base + j) << 19) | 0x7FFFFu);
            m = (double)hv[j] * exp(((double)xr - (double)xmax) * invd);
        }
        mv[j] = m; csum += m;
    }
    sarr[tid] = csum; __syncthreads();
    for (int off = 1; off < 1024; off <<= 1){
        double v = sarr[tid];
        double a = (tid + off < 1024) ? sarr[tid + off] : 0.0;
        __syncthreads();
        sarr[tid] = v + a;
        __syncthreads();
    }
    double above = sarr[tid] - csum;
    if (tid == 0) sZ = sarr[0];
    __syncthreads();
    double Z = sZ;

    float p = fminf(fmaxf(topps[row], 0.0f), 1.0f);
    double pZ = (double)p * Z;

    int bestj = -1; double bestAbove = 0.0;
    double run = above;
    for (int j = 7; j >= 0; j--){
        double s = mv[j];
        if (run + s > pZ){ bestj = base + j; bestAbove = run; break; }
        run += s;
    }
    __syncthreads();
    sbi[tid] = bestj; sarr[tid] = bestAbove; __syncthreads();
    for (int s2 = 512; s2 > 0; s2 >>= 1){
        if (tid < s2 && sbi[tid + s2] > sbi[tid]){
            sbi[tid] = sbi[tid + s2];
            sarr[tid] = sarr[tid + s2];
        }
        __syncthreads();
    }
    if (tid == 0){
        int B = sbi[0];
        // degenerate: the max's own bin underflowed, or scan failed
        bool deg = (g_histG[(size_t)row * NBINS + (kmax >> 19)] == 0.0f) || (B < 0);
        if (deg){
            g_Bstar[row] = -2;          // keep only max ties (one-hot softmax)
            g_cumAbove[row] = 0.0;
            g_Z[row] = 0.0;
        } else {
            g_Bstar[row] = B;
            g_cumAbove[row] = sarr[0];
            g_Z[row] = Z;
        }
    }
}

// ---------------- K3a: gather keeps + candidates + max ties (float-cmp) ------
__global__ void k3a_gather(const float* __restrict__ logits,
                           const float* __restrict__ temps){
    int row = blockIdx.y;
    int B = g_Bstar[row];
    unsigned kmax = g_rmk[row];
    int Bstar = (B == -2) ? (int)(kmax >> 19) : B;
    float t = temps[row]; float ts = (t == 0.0f) ? 1.0f : t;
    float xmaxv = key_to_float(kmax);
    // float thresholds for the hot path (monotone <=> okey order; NaN-free data)
    float candLo = key_to_float((unsigned)Bstar << 19);
    float keepLo = (Bstar >= 0x1FFF) ? __int_as_float(0x7f800000)
                                     : key_to_float((unsigned)(Bstar + 1) << 19);

    int base0 = blockIdx.x * 16000;                  // 8 chunks per row
    const float4* x4 = (const float4*)(logits + (size_t)row * VOCAB + base0);
    __shared__ ull sbuf[SBUF];                       // 32KB staging
    __shared__ int scnt, sbase;
    if (threadIdx.x == 0) scnt = 0;
    __syncthreads();
    ull* keepRow = g_keep + (size_t)row * VOCAB;
    ull* candRow = g_cand + (size_t)row * CAP;

    for (int i0 = 0; i0 < 4000; i0 += 1024){
        float4 f[4]; bool ok[4];
#pragma unroll
        for (int k = 0; k < 4; k++){
            int i = i0 + threadIdx.x + k * 256;
            ok[k] = (i < 4000);
            if (ok[k]) f[k] = x4[i];
        }
#pragma unroll
        for (int k = 0; k < 4; k++){
            if (!ok[k]) continue;
            unsigned v0 = (unsigned)(base0 + (i0 + threadIdx.x + k * 256) * 4);
            float vals[4] = {f[k].x, f[k].y, f[k].z, f[k].w};
#pragma unroll
            for (int j = 0; j < 4; j++){
                float x = vals[j];
                unsigned v = v0 + j;
                if (x >= keepLo){
                    int pos = atomicAdd(&scnt, 1);
                    sbuf[pos] = ((ull)okey(x) << 32) | v;
                } else if (x >= candLo){
                    int pos = atomicAdd(&g_ccount[row], 1);
                    if (pos < CAP){
                        float s = __fdiv_rn(x, ts);
                        candRow[pos] = ((ull)okey(s) << 32) | v;
                    }
                }
                if (x == xmaxv) atomicMin(&g_amin[row], v);
            }
        }
        __syncthreads();
        int n = scnt;
        if (n > 0){
            if (threadIdx.x == 0){
                sbase = atomicAdd(&g_kcount[row], n);
                scnt = 0;
            }
            __syncthreads();
            for (int i = threadIdx.x; i < n; i += 256)
                keepRow[sbase + i] = sbuf[i];
        }
        __syncthreads();
    }
}

// ---------------- K3b: sort candidates + exact cutoff ------------------------
__global__ void k3b_cut(const float* __restrict__ temps,
                        const float* __restrict__ topps){
    int row = blockIdx.x;
    int B = g_Bstar[row];
    unsigned kmax = g_rmk[row];
    int Bstar = (B == -2) ? (int)(kmax >> 19) : B;
    __shared__ ull keys[CAP];                 // 32KB
    __shared__ double sarr[1024];
    __shared__ int sli[1024];

    float t = temps[row]; float ts = (t == 0.0f) ? 1.0f : t;
    double Ms = (double)__fdiv_rn(key_to_float(kmax), ts);
    int count = min(g_ccount[row], CAP);
    if (count == 0){                          // guard; ~never (bin non-empty)
        if (threadIdx.x == 0){
            float xLo = key_to_float((unsigned)Bstar << 19);
            g_cut[row] = ((ull)okey(__fdiv_rn(xLo, ts)) << 32);
        }
        return;
    }
    int n = 1; while (n < count) n <<= 1; if (n < 2) n = 2;
    for (int i = threadIdx.x; i < n; i += blockDim.x)
        keys[i] = (i < count) ? g_cand[(size_t)row * CAP + i] : 0ULL;
    __syncthreads();

    // bitonic sort DESCENDING on packed (okey(s), idx)
    for (int k2 = 2; k2 <= n; k2 <<= 1){
        for (int j = k2 >> 1; j > 0; j >>= 1){
            for (int i = threadIdx.x; i < n; i += blockDim.x){
                int ixj = i ^ j;
                if (ixj > i){
                    ull a = keys[i], b = keys[ixj];
                    bool seg = ((i & k2) == 0);
                    if (seg ? (a < b) : (a > b)){ keys[i] = b; keys[ixj] = a; }
                }
            }
            __syncthreads();
        }
    }

    double pZ = (double)fminf(fmaxf(topps[row], 0.0f), 1.0f) * g_Z[row];
    double cumAbove = g_cumAbove[row];
    int m = (n + blockDim.x - 1) / blockDim.x;   // <= 4
    int lo = threadIdx.x * m;
    double ev[4];
    double ls = 0.0;
    for (int q = 0; q < m; q++){
        int i = lo + q; double e = 0.0;
        if (i < count){
            double sv = (double)key_to_float((unsigned)(keys[i] >> 32));
            e = exp(sv - Ms);
        }
        ev[q] = e; ls += e;
    }
    sarr[threadIdx.x] = ls; __syncthreads();
    for (int off = 1; off < 1024; off <<= 1){
        double v = sarr[threadIdx.x];
        double a = (threadIdx.x >= off) ? sarr[threadIdx.x - off] : 0.0;
        __syncthreads();
        sarr[threadIdx.x] = v + a;
        __syncthreads();
    }
    double run = sarr[threadIdx.x] - ls + cumAbove;
    int lastKept = -1;
    for (int q = 0; q < m; q++){
        int i = lo + q;
        run += ev[q];
        if (i < count && run <= pZ) lastKept = i;
    }
    sli[threadIdx.x] = lastKept; __syncthreads();
    for (int s2 = 512; s2 > 0; s2 >>= 1){
        if (threadIdx.x < s2)
            sli[threadIdx.x] = max(sli[threadIdx.x], sli[threadIdx.x + s2]);
        __syncthreads();
    }
    if (threadIdx.x == 0){
        int iL = sli[0];
        ull C;
        if (iL >= 0)             C = keys[iL];
        else if (cumAbove > 0.0){
            float xHi = key_to_float((unsigned)(Bstar + 1) << 19);
            C = ((ull)okey(__fdiv_rn(xHi, ts)) << 32);
        } else                   C = keys[0];  // force-keep top element (ties: largest idx)
        g_cut[row] = C;
    }
}

// ---------------- K4a: gumbel-max over COMPACTED kept set --------------------
__global__ void k4a_compact(const float* __restrict__ temps){
    int row = blockIdx.y;
    int nk = g_kcount[row];
    int nc = min(g_ccount[row], CAP);
    int tot = nk + nc;
    float t = temps[row]; float ts = (t == 0.0f) ? 1.0f : t;
    float Ms = __fdiv_rn(key_to_float(g_rmk[row]), ts);
    ull C = g_cut[row];
    unsigned iBase = (unsigned)row * (unsigned)VOCAB;
    const ull* keepRow = g_keep + (size_t)row * VOCAB;
    const ull* candRow = g_cand + (size_t)row * CAP;

    float sk = 0.0f; ull bestp = 0ULL;
    for (int i = blockIdx.x * 256 + threadIdx.x; i < tot; i += 1024){
        float s; unsigned v; bool kept;
        if (i < nk){
            ull e = keepRow[i];
            v = (unsigned)e;
            s = __fdiv_rn(key_to_float((unsigned)(e >> 32)), ts);
            kept = true;
        } else {
            ull e = candRow[i - nk];
            v = (unsigned)e;
            s = key_to_float((unsigned)(e >> 32));
            kept = (e >= C);
        }
        if (kept){
            sk += __expf(s - Ms);
            float sc = s + gumbel_from_bits(jax_bits32(iBase + v));
            ull p = ((ull)okey(sc) << 32) | (unsigned)(~v);
            if (p > bestp) bestp = p;
        }
    }

    __shared__ ull sp[256];
    __shared__ float sv[256];
    sp[threadIdx.x] = bestp; sv[threadIdx.x] = sk;
    __syncthreads();
    for (int s = 128; s > 0; s >>= 1){
        if (threadIdx.x < s){
            if (sp[threadIdx.x + s] > sp[threadIdx.x])
                sp[threadIdx.x] = sp[threadIdx.x + s];
            sv[threadIdx.x] += sv[threadIdx.x + s];
        }
        __syncthreads();
    }
    if (threadIdx.x == 0){
        if (sp[0] != 0ULL) atomicMax(&g_best[row], sp[0]);
        if (sv[0] != 0.0f) atomicAdd(&g_sk[row], sv[0]);
    }
}

// ---------------- K4b: finalize ----------------------------------------------
__global__ void k4b_final(const float* __restrict__ logits,
                          const float* __restrict__ temps,
                          float* __restrict__ out){
    int row = threadIdx.x;   // 256 threads, 1 block
    if (row >= BATCH) return;
    float t = temps[row]; float ts = (t == 0.0f) ? 1.0f : t;
    float Ms = __fdiv_rn(key_to_float(g_rmk[row]), ts);
    unsigned greedy = g_amin[row];
    ull C = g_cut[row];
    unsigned tok;
    if (t == 0.0f) tok = greedy;
    else {
        unsigned cand = ~(unsigned)(g_best[row] & 0xFFFFFFFFu);
        tok = (cand < (unsigned)VOCAB) ? cand : greedy;
    }
    float stok = __fdiv_rn(logits[(size_t)row * VOCAB + tok], ts);
    ull pT = ((ull)okey(stok) << 32) | tok;
    float sel = (pT >= C) ? stok : NEG_INF;
    float skv = g_sk[row];
    float lp = (skv > 0.0f) ? (sel - (Ms + logf(skv))) : 0.0f;
    out[row]          = (float)tok;
    out[BATCH + row]  = lp;
}

// ---------------- launch -----------------------------------------------------
extern "C" void kernel_launch(void* const* d_in, const int* in_sizes, int n_in,
                              void* d_out, int out_size){
    const float* logits = (const float*)d_in[0];
    const float* temps  = (const float*)d_in[1];
    const float* topps  = (const float*)d_in[2];
    float* out = (float*)d_out;

    k0_init    <<<512, 1024>>>();
    k2a_hist   <<<dim3(4, BATCH), 512>>>(logits, temps);
    k2b_scan   <<<BATCH, 1024>>>(temps, topps);
    k3a_gather <<<dim3(8, BATCH), 256>>>(logits, temps);
    k3b_cut    <<<BATCH, 1024>>>(temps, topps);
    k4a_compact<<<dim3(4, BATCH), 256>>>(temps);
    k4b_final  <<<1, 256>>>(logits, temps, out);
}

// round 7
// speedup vs baseline: 1.1880x; 1.0183x over previous
#include <cuda_runtime.h>
#include <math.h>
#include <stdint.h>

#define BATCH 256
#define VOCAB 128000
#define NBINS 8192
#define CAP   4096
#define NEG_INF __int_as_float(0xff800000)
typedef unsigned long long ull;

// ---------------- scratch (device globals; no allocations allowed) ----------
__device__ float    g_histG[BATCH * NBINS];          // 8MB merged histograms
__device__ ull      g_cand[BATCH * CAP];             // boundary-bin candidates
__device__ int      g_ccount[BATCH];
__device__ unsigned g_rmk[BATCH];                    // okey(row max value)
__device__ unsigned g_amin[BATCH];                   // argmax (first occurrence)
__device__ ull      g_best[BATCH];                   // (okey(score)<<32)|~v
__device__ float    g_sk[BATCH];                     // kept mass (Ms-anchored)
__device__ int      g_Bstar[BATCH];                  // -2 = degenerate row
__device__ double   g_cumAbove[BATCH];
__device__ double   g_Z[BATCH];

// monotone float<->uint key (total order)
__device__ __forceinline__ unsigned okey(float f){
    unsigned b = __float_as_uint(f);
    return b ^ ((b & 0x80000000u) ? 0xFFFFFFFFu : 0x80000000u);
}
__device__ __forceinline__ float key_to_float(unsigned k){
    unsigned b = (k & 0x80000000u) ? (k ^ 0x80000000u) : ~k;
    return __uint_as_float(b);
}
__device__ __forceinline__ float ex2(float x){      // single MUFU.EX2
    float r; asm("ex2.approx.f32 %0, %1;" : "=f"(r) : "f"(x)); return r;
}

// jax threefry2x32-20, key = (0, 42)
__device__ __forceinline__ void threefry(unsigned c0, unsigned c1,
                                         unsigned &o0, unsigned &o1){
    const unsigned k0 = 0u, k1 = 42u;
    const unsigned k2 = 0x1BD11BDAu ^ k0 ^ k1;
    unsigned x0 = c0 + k0, x1 = c1 + k1;
#define TFR(r) { x0 += x1; x1 = ((x1 << r) | (x1 >> (32 - r))); x1 ^= x0; }
    TFR(13) TFR(15) TFR(26) TFR(6)   x0 += k1; x1 += k2 + 1u;
    TFR(17) TFR(29) TFR(16) TFR(24)  x0 += k2; x1 += k0 + 2u;
    TFR(13) TFR(15) TFR(26) TFR(6)   x0 += k0; x1 += k1 + 3u;
    TFR(17) TFR(29) TFR(16) TFR(24)  x0 += k1; x1 += k2 + 4u;
    TFR(13) TFR(15) TFR(26) TFR(6)   x0 += k2; x1 += k0 + 5u;
#undef TFR
    o0 = x0; o1 = x1;
}
__device__ __forceinline__ unsigned jax_bits32(unsigned i){
    unsigned o0, o1; threefry(0u, i, o0, o1); return o0 ^ o1;
}
__device__ __forceinline__ float gumbel_from_bits(unsigned bits){
    float u = __uint_as_float((bits >> 9) | 0x3f800000u) - 1.0f;
    if (u <= 0.0f) u = 1.17549435e-38f;
    float inner = -log1pf(u - 1.0f);   // == -log(u) exactly
    return -logf(inner);
}
__device__ __forceinline__ float bin_top(unsigned bin){   // bin top-edge value
    return key_to_float((bin << 19) | 0x7FFFFu);
}

// ---------------- K0: init ---------------------------------------------------
__global__ void k0_init(){
    size_t id = (size_t)blockIdx.x * 1024 + threadIdx.x;
    float4* h4 = (float4*)g_histG;
    if (id < (size_t)BATCH * NBINS / 4) h4[id] = make_float4(0.f,0.f,0.f,0.f);
    if (id < BATCH){
        g_rmk[id] = 0u; g_amin[id] = 0xFFFFFFFFu;
        g_best[id] = 0ULL; g_sk[id] = 0.0f;
        g_ccount[id] = 0;
    }
}

// ---------------- K2a: raw-key weighted histogram + row max ------------------
__global__ void k2a_hist(const float* __restrict__ logits,
                         const float* __restrict__ temps){
    int row = blockIdx.y, part = blockIdx.x;        // 2 parts of 64000 elems
    __shared__ float bins[NBINS];                   // 32KB only
    __shared__ float sm[512];
    for (int i = threadIdx.x; i < NBINS; i += 512) bins[i] = 0.0f;
    __syncthreads();

    float t = temps[row]; float ts = (t == 0.0f) ? 1.0f : t;
    float c1 = __fdividef(1.4426950408889634f, ts);     // log2e / ts
    const float4* x4 = (const float4*)(logits + (size_t)row * VOCAB + part * 64000);
    float vmax = NEG_INF;
    for (int base = threadIdx.x; base < 16000; base += 2048){
        float4 f[4]; bool ok[4];
#pragma unroll
        for (int k = 0; k < 4; k++){
            int i = base + k * 512;
            ok[k] = (i < 16000);
            if (ok[k]) f[k] = x4[i];
        }
#pragma unroll
        for (int k = 0; k < 4; k++){
            if (!ok[k]) continue;
            float vals[4] = {f[k].x, f[k].y, f[k].z, f[k].w};
#pragma unroll
            for (int j = 0; j < 4; j++){
                float x = vals[j];
                vmax = fmaxf(vmax, x);
                unsigned bin = okey(x) >> 19;
                float d = x - bin_top(bin);         // exact (same binade)
                atomicAdd(&bins[bin], ex2(d * c1));
            }
        }
    }
    sm[threadIdx.x] = vmax; __syncthreads();
    for (int s = 256; s > 0; s >>= 1){
        if (threadIdx.x < s) sm[threadIdx.x] = fmaxf(sm[threadIdx.x], sm[threadIdx.x + s]);
        __syncthreads();
    }
    if (threadIdx.x == 0) atomicMax(&g_rmk[row], okey(sm[0]));
    float* gh = g_histG + (size_t)row * NBINS;
    for (int i = threadIdx.x; i < NBINS; i += 512)
        if (bins[i] != 0.0f) atomicAdd(&gh[i], bins[i]);
}

// ---------------- K2b: rescale + suffix scan -> boundary bin -----------------
__global__ void k2b_scan(const float* __restrict__ temps,
                         const float* __restrict__ topps){
    int row = blockIdx.x; int tid = threadIdx.x;   // 1024 threads
    __shared__ double sarr[1024];
    __shared__ int    sbi[1024];
    __shared__ double sZ;

    float t = temps[row]; float ts = (t == 0.0f) ? 1.0f : t;
    unsigned kmax = g_rmk[row];
    float xmax = key_to_float(kmax);
    double invd = 1.0 / (double)ts;

    const float4* gh4 = (const float4*)(g_histG + (size_t)row * NBINS);
    float4 h0 = gh4[tid * 2], h1 = gh4[tid * 2 + 1];
    float hv[8] = {h0.x, h0.y, h0.z, h0.w, h1.x, h1.y, h1.z, h1.w};

    int base = tid * 8;
    double mv[8]; double csum = 0.0;
#pragma unroll
    for (int j = 0; j < 8; j++){
        double m = 0.0;
        if (hv[j] > 0.0f){
            double arg = ((double)bin_top((unsigned)(base + j)) - (double)xmax) * invd;
            if (arg > -80.0) m = (double)hv[j] * exp(arg);  // gated f64 exp
        }
        mv[j] = m; csum += m;
    }
    sarr[tid] = csum; __syncthreads();
    for (int off = 1; off < 1024; off <<= 1){
        double v = sarr[tid];
        double a = (tid + off < 1024) ? sarr[tid + off] : 0.0;
        __syncthreads();
        sarr[tid] = v + a;
        __syncthreads();
    }
    double above = sarr[tid] - csum;
    if (tid == 0) sZ = sarr[0];
    __syncthreads();
    double Z = sZ;

    float p = fminf(fmaxf(topps[row], 0.0f), 1.0f);
    double pZ = (double)p * Z;

    int bestj = -1; double bestAbove = 0.0;
    double run = above;
    for (int j = 7; j >= 0; j--){
        double s = mv[j];
        if (run + s > pZ){ bestj = base + j; bestAbove = run; break; }
        run += s;
    }
    __syncthreads();
    sbi[tid] = bestj; sarr[tid] = bestAbove; __syncthreads();
    for (int s2 = 512; s2 > 0; s2 >>= 1){
        if (tid < s2 && sbi[tid + s2] > sbi[tid]){
            sbi[tid] = sbi[tid + s2];
            sarr[tid] = sarr[tid + s2];
        }
        __syncthreads();
    }
    if (tid == 0){
        int B = sbi[0];
        bool deg = (g_histG[(size_t)row * NBINS + (kmax >> 19)] == 0.0f) || (B < 0);
        if (deg){
            g_Bstar[row] = -2;          // keep only top max-bin element
            g_cumAbove[row] = 0.0;
            g_Z[row] = 0.0;
        } else {
            g_Bstar[row] = B;
            g_cumAbove[row] = sarr[0];
            g_Z[row] = Z;
        }
    }
}

// ---------------- K3: stream — gumbel over sure-keeps + gather candidates ----
__global__ void k3_stream(const float* __restrict__ logits,
                          const float* __restrict__ temps){
    int row = blockIdx.y;
    int B = g_Bstar[row];
    unsigned kmax = g_rmk[row];
    int Bstar = (B == -2) ? (int)(kmax >> 19) : B;
    float t = temps[row]; float ts = (t == 0.0f) ? 1.0f : t;
    float Ms = __fdiv_rn(key_to_float(kmax), ts);
    float xmaxv = key_to_float(kmax);
    // float thresholds (monotone with okey; data NaN-free)
    float candLo = key_to_float((unsigned)Bstar << 19);
    float keepLo = (Bstar >= 0x1FEF) ? __int_as_float(0x7f800000)
                                     : key_to_float((unsigned)(Bstar + 1) << 19);

    int base0 = blockIdx.x * 16000;                  // 8 chunks per row
    const float4* x4 = (const float4*)(logits + (size_t)row * VOCAB + base0);
    ull* candRow = g_cand + (size_t)row * CAP;
    unsigned iBase = (unsigned)row * (unsigned)VOCAB;

    float sk = 0.0f; ull bestp = 0ULL;
    for (int i0 = 0; i0 < 4000; i0 += 1024){
        float4 f[4]; bool ok[4];
#pragma unroll
        for (int k = 0; k < 4; k++){
            int i = i0 + threadIdx.x + k * 256;
            ok[k] = (i < 4000);
            if (ok[k]) f[k] = x4[i];
        }
#pragma unroll
        for (int k = 0; k < 4; k++){
            if (!ok[k]) continue;
            unsigned v0 = (unsigned)(base0 + (i0 + threadIdx.x + k * 256) * 4);
            float vals[4] = {f[k].x, f[k].y, f[k].z, f[k].w};
#pragma unroll
            for (int j = 0; j < 4; j++){
                float x = vals[j];
                unsigned v = v0 + j;
                if (x >= keepLo){
                    // certainly kept: contribute inline
                    float s = __fdiv_rn(x, ts);
                    sk += __expf(s - Ms);
                    float sc = s + gumbel_from_bits(jax_bits32(iBase + v));
                    ull p = ((ull)okey(sc) << 32) | (unsigned)(~v);
                    if (p > bestp) bestp = p;
                } else if (x >= candLo){
                    int pos = atomicAdd(&g_ccount[row], 1);
                    if (pos < CAP){
                        float s = __fdiv_rn(x, ts);
                        candRow[pos] = ((ull)okey(s) << 32) | v;
                    }
                }
                if (x == xmaxv) atomicMin(&g_amin[row], v);
            }
        }
    }

    __shared__ ull sp[256];
    __shared__ float sv[256];
    sp[threadIdx.x] = bestp; sv[threadIdx.x] = sk;
    __syncthreads();
    for (int s = 128; s > 0; s >>= 1){
        if (threadIdx.x < s){
            if (sp[threadIdx.x + s] > sp[threadIdx.x])
                sp[threadIdx.x] = sp[threadIdx.x + s];
            sv[threadIdx.x] += sv[threadIdx.x + s];
        }
        __syncthreads();
    }
    if (threadIdx.x == 0){
        if (sp[0] != 0ULL) atomicMax(&g_best[row], sp[0]);
        if (sv[0] != 0.0f) atomicAdd(&g_sk[row], sv[0]);
    }
}

// ---------------- K4: per-row finalize — sort cands, cut, sample, output -----
__global__ void k4_final(const float* __restrict__ logits,
                         const float* __restrict__ temps,
                         const float* __restrict__ topps,
                         float* __restrict__ out){
    int row = blockIdx.x;
    int B = g_Bstar[row];
    unsigned kmax = g_rmk[row];
    int Bstar = (B == -2) ? (int)(kmax >> 19) : B;
    __shared__ ull keys[CAP];                 // 32KB
    __shared__ double sarr[1024];
    __shared__ int sli[1024];
    __shared__ ull sC;

    float t = temps[row]; float ts = (t == 0.0f) ? 1.0f : t;
    float Ms = __fdiv_rn(key_to_float(kmax), ts);
    int count = min(g_ccount[row], CAP);
    unsigned iBase = (unsigned)row * (unsigned)VOCAB;

    if (count == 0){                          // guard; ~never (bin non-empty)
        if (threadIdx.x == 0)
            sC = ((ull)okey(__fdiv_rn(key_to_float((unsigned)Bstar << 19), ts)) << 32);
    } else {
        int n = 1; while (n < count) n <<= 1; if (n < 2) n = 2;
        for (int i = threadIdx.x; i < n; i += blockDim.x)
            keys[i] = (i < count) ? g_cand[(size_t)row * CAP + i] : 0ULL;
        __syncthreads();

        // bitonic sort DESCENDING on packed (okey(s), idx)
        for (int k2 = 2; k2 <= n; k2 <<= 1){
            for (int j = k2 >> 1; j > 0; j >>= 1){
                for (int i = threadIdx.x; i < n; i += blockDim.x){
                    int ixj = i ^ j;
                    if (ixj > i){
                        ull a = keys[i], b = keys[ixj];
                        bool seg = ((i & k2) == 0);
                        if (seg ? (a < b) : (a > b)){ keys[i] = b; keys[ixj] = a; }
                    }
                }
                __syncthreads();
            }
        }

        double pZ = (double)fminf(fmaxf(topps[row], 0.0f), 1.0f) * g_Z[row];
        double cumAbove = g_cumAbove[row];
        int m = (n + 1023) / 1024;   // <= 4
        int lo = threadIdx.x * m;
        double ev[4];
        double ls = 0.0;
        for (int q = 0; q < m; q++){
            int i = lo + q; double e = 0.0;
            if (i < count){
                double sv2 = (double)key_to_float((unsigned)(keys[i] >> 32));
                e = exp(sv2 - (double)Ms);
            }
            ev[q] = e; ls += e;
        }
        sarr[threadIdx.x] = ls; __syncthreads();
        for (int off = 1; off < 1024; off <<= 1){
            double v = sarr[threadIdx.x];
            double a = (threadIdx.x >= off) ? sarr[threadIdx.x - off] : 0.0;
            __syncthreads();
            sarr[threadIdx.x] = v + a;
            __syncthreads();
        }
        double run = sarr[threadIdx.x] - ls + cumAbove;
        int lastKept = -1;
        for (int q = 0; q < m; q++){
            int i = lo + q;
            run += ev[q];
            if (i < count && run <= pZ) lastKept = i;
        }
        sli[threadIdx.x] = lastKept; __syncthreads();
        for (int s2 = 512; s2 > 0; s2 >>= 1){
            if (threadIdx.x < s2)
                sli[threadIdx.x] = max(sli[threadIdx.x], sli[threadIdx.x + s2]);
            __syncthreads();
        }
        if (threadIdx.x == 0){
            int iL = sli[0];
            ull C;
            if (iL >= 0)                      C = keys[iL];
            else if (g_cumAbove[row] > 0.0){
                float xHi = key_to_float((unsigned)(Bstar + 1) << 19);
                C = ((ull)okey(__fdiv_rn(xHi, ts)) << 32);
            } else                            C = keys[0];  // keep top element
            sC = C;
        }
    }
    __syncthreads();
    ull C = sC;

    // candidate contributions (kept subset)
    float sk = 0.0f; ull bestp = 0ULL;
    for (int i = threadIdx.x; i < count; i += 1024){
        ull e = keys[i];                   // sorted copy still in smem
        if (e >= C){
            unsigned v = (unsigned)e;
            float s = key_to_float((unsigned)(e >> 32));
            sk += __expf(s - Ms);
            float sc = s + gumbel_from_bits(jax_bits32(iBase + v));
            ull p = ((ull)okey(sc) << 32) | (unsigned)(~v);
            if (p > bestp) bestp = p;
        }
    }
    __shared__ ull sp[1024];
    __shared__ float svf[1024];
    sp[threadIdx.x] = bestp; svf[threadIdx.x] = sk;
    __syncthreads();
    for (int s = 512; s > 0; s >>= 1){
        if (threadIdx.x < s){
            if (sp[threadIdx.x + s] > sp[threadIdx.x])
                sp[threadIdx.x] = sp[threadIdx.x + s];
            svf[threadIdx.x] += svf[threadIdx.x + s];
        }
        __syncthreads();
    }

    if (threadIdx.x == 0){
        ull bestAll = g_best[row];
        if (sp[0] > bestAll) bestAll = sp[0];
        float skAll = g_sk[row] + svf[0];
        unsigned greedy = g_amin[row];
        unsigned tok;
        if (t == 0.0f) tok = greedy;
        else {
            unsigned cand = ~(unsigned)(bestAll & 0xFFFFFFFFu);
            tok = (cand < (unsigned)VOCAB) ? cand : greedy;
        }
        float stok = __fdiv_rn(logits[(size_t)row * VOCAB + tok], ts);
        ull pT = ((ull)okey(stok) << 32) | tok;
        float sel = (pT >= C) ? stok : NEG_INF;
        float lp = (skAll > 0.0f) ? (sel - (Ms + logf(skAll))) : 0.0f;
        out[row]          = (float)tok;
        out[BATCH + row]  = lp;
    }
}

// ---------------- launch -----------------------------------------------------
extern "C" void kernel_launch(void* const* d_in, const int* in_sizes, int n_in,
                              void* d_out, int out_size){
    const float* logits = (const float*)d_in[0];
    const float* temps  = (const float*)d_in[1];
    const float* topps  = (const float*)d_in[2];
    float* out = (float*)d_out;

    k0_init  <<<512, 1024>>>();
    k2a_hist <<<dim3(2, BATCH), 512>>>(logits, temps);
    k2b_scan <<<BATCH, 1024>>>(temps, topps);
    k3_stream<<<dim3(8, BATCH), 256>>>(logits, temps);
    k4_final <<<BATCH, 1024>>>(logits, temps, topps, out);
}